// round 15
// baseline (speedup 1.0000x reference)
#include <cuda_runtime.h>
#include <math.h>

// Problem constants (fixed by the bench problem)
#define AA     48          // atoms per batch
#define SS     4           // num species
#define NR     16          // num radial shifts
#define NAA    4           // num angular radial shifts
#define NZ     8           // num angular shifts
#define NPAIRS (SS*(SS+1)/2)   // 10
#define RADD   (SS*NR)         // 64
#define ANGD   (NPAIRS*NAA*NZ) // 320
#define OUTD   (RADD+ANGD)     // 384
#define RCR    5.2f
#define RCA    3.5f
#define PI_F   3.14159265358979323846f

__global__ __launch_bounds__(384) void aev_kernel(
    const int*   __restrict__ species,   // [B, A]
    const float* __restrict__ coords,    // [B, A, 3]
    const float* __restrict__ EtaR,      // [1]
    const float* __restrict__ ShfR,      // [NR]
    const float* __restrict__ EtaA,      // [1]
    const float* __restrict__ Zeta,      // [1]
    const float* __restrict__ ShfA,      // [NAA]
    const float* __restrict__ ShfZ,      // [NZ]
    float*       __restrict__ out)       // [B, A, OUTD] (pre-zeroed)
{
    // unified compacted neighbor lists
    __shared__ float4 avec[AA];         // angular: unit dx,dy,dz, d
    __shared__ float  afcs[AA];         // angular: fc
    __shared__ int    aspc[AA];         // angular: species
    __shared__ float2 rlst[AA];         // radial:  d, fc
    __shared__ int    rspc[AA];         // radial:  species
    __shared__ int    cntR, cntA;

    const int tid  = threadIdx.x;
    const int wid  = tid >> 5;
    const int lane = tid & 31;
    const int aidx = blockIdx.x;
    const int i    = aidx % AA;
    const int b    = aidx / AA;

    // ---- params -> registers ----
    const float etaR = EtaR[0];
    const float etaA = EtaA[0];
    const float zeta = Zeta[0];
    const float shfr = ShfR[tid & 15];          // constant per thread (384 % 16 == 0)
    const float shfa = ShfA[lane >> 3];         // angular feature (a,z)
    const float shz  = ShfZ[lane & 7];
    const float cz   = __cosf(shz);
    const float sz   = __sinf(shz);

    if (tid == 383) { cntR = 0; cntA = 0; }

    // ---- distances in registers (threads 0..47) ----
    float uxr=0, uyr=0, uzr=0, drr=0, fcrv=0, fcav=0;
    bool  pvR=false, pvA=false;
    int   spj=0;
    if (tid < AA) {
        int j = tid;
        const float* cb = coords + (size_t)b*AA*3;
        float xi = cb[3*i], yi = cb[3*i+1], zi = cb[3*i+2];
        float dx = xi - cb[3*j], dy = yi - cb[3*j+1], dz = zi - cb[3*j+2];
        float d2 = dx*dx + dy*dy + dz*dz;
        float d  = sqrtf(d2);
        spj = species[b*AA + j];
        int spi = species[b*AA + i];
        bool pv = (spi >= 0) && (spj >= 0) && (j != i);
        drr = d;
        pvR = pv && (d <= RCR);
        pvA = pv && (d <= RCA);
        fcrv = 0.5f*__cosf(PI_F * d * (1.0f/RCR)) + 0.5f;
        fcav = 0.5f*__cosf(PI_F * d * (1.0f/RCA)) + 0.5f;
        float invd = __frsqrt_rn(fmaxf(d2, 1e-12f));
        uxr = dx*invd; uyr = dy*invd; uzr = dz*invd;
    }
    __syncthreads();   // #1: counters ready

    // ---- compaction (unified lists) ----
    if (tid < AA) {
        if (pvR) {
            int s = atomicAdd(&cntR, 1);
            rlst[s] = make_float2(drr, fcrv);
            rspc[s] = spj;
        }
        if (pvA) {
            int s = atomicAdd(&cntA, 1);
            avec[s] = make_float4(uxr, uyr, uzr, drr);
            afcs[s] = fcav;
            aspc[s] = spj;
        }
    }
    __syncthreads();   // #2: lists ready

    const int M      = cntA;
    const int Mr     = cntR;
    const int npair2 = M*(M-1)/2;
    const float twoM1 = (float)(2*M - 1);
    float* o = out + (size_t)aidx * OUTD;

    // ---- radial: thread-item pool, RED accumulate (r = tid&15 fixed) ----
    for (int w = tid; w < Mr*NR; w += 384) {
        int k = w >> 4;
        float2 v  = rlst[k];
        float  dd = v.x - shfr;
        atomicAdd(&o[rspc[k]*NR + (tid & 15)],
                  0.25f * __expf(-etaR * dd * dd) * v.y);
    }

    // ---- angular: all 12 warps draw from the unified pair pool ----
    for (int u = wid; u < npair2; u += 12) {
        // closed-form decode of (p,q), warp-uniform
        float disc = fmaxf(twoM1*twoM1 - 8.0f*(float)u, 0.0f);
        int p = (int)floorf((twoM1 - __fsqrt_rn(disc)) * 0.5f);
        if (p > M-2) p = M-2;
        if ((p+1)*(2*M - p - 2) / 2 <= u) p++;
        if (p*(2*M - p - 1) / 2 > u) p--;
        int q = u - p*(2*M - p - 1)/2 + p + 1;

        float4 P = avec[p];
        float4 Q = avec[q];
        float fcp = afcs[p], fcq = afcs[q];
        float cosA = 0.95f * (P.x*Q.x + P.y*Q.y + P.z*Q.z);
        float sinA = sqrtf(fmaxf(1.0f - cosA*cosA, 0.0f));
        float t    = 0.5f*(P.w + Q.w) - shfa;
        float f2   = 2.0f * fcp * fcq * __expf(-etaA * t * t);
        float x    = 0.5f + 0.5f*(cosA*cz + sinA*sz);
        float f1;
        if (zeta == 32.0f) {
            float x2 = x*x, x4 = x2*x2, x8 = x4*x4, x16 = x8*x8;
            f1 = x16*x16;
        } else {
            f1 = __powf(x, zeta);
        }

        int s1 = aspc[p], s2 = aspc[q];
        int lo = min(s1, s2), hi = max(s1, s2);
        int pidx = lo*SS - (lo*(lo-1))/2 + (hi - lo);

        atomicAdd(&o[RADD + pidx*32 + lane], f1 * f2);
    }
    // no final barrier, no store phase — warps retire independently
}

extern "C" void kernel_launch(void* const* d_in, const int* in_sizes, int n_in,
                              void* d_out, int out_size)
{
    const int*   species = (const int*)  d_in[0];
    const float* coords  = (const float*)d_in[1];
    const float* EtaR    = (const float*)d_in[2];
    const float* ShfR    = (const float*)d_in[3];
    const float* EtaA    = (const float*)d_in[4];
    const float* Zeta    = (const float*)d_in[5];
    const float* ShfA    = (const float*)d_in[6];
    const float* ShfZ    = (const float*)d_in[7];
    float* out = (float*)d_out;

    int B = in_sizes[0] / AA;   // species is [B, A]
    // graph-captured memset node: zero the accumulation target
    cudaMemsetAsync(d_out, 0, (size_t)out_size * sizeof(float));
    aev_kernel<<<B * AA, 384>>>(species, coords, EtaR, ShfR, EtaA, Zeta,
                                ShfA, ShfZ, out);
}

// round 16
// speedup vs baseline: 1.0690x; 1.0690x over previous
#include <cuda_runtime.h>
#include <math.h>

// Problem constants (fixed by the bench problem)
#define AA     48          // atoms per batch
#define SS     4           // num species
#define NR     16          // num radial shifts
#define NAA    4           // num angular radial shifts
#define NZ     8           // num angular shifts
#define NPAIRS (SS*(SS+1)/2)   // 10
#define RADD   (SS*NR)         // 64
#define ANGD   (NPAIRS*NAA*NZ) // 320
#define OUTD   (RADD+ANGD)     // 384
#define RCR    5.2f
#define RCA    3.5f
#define PI_F   3.14159265358979323846f

__global__ __launch_bounds__(384) void aev_kernel(
    const int*   __restrict__ species,   // [B, A]
    const float* __restrict__ coords,    // [B, A, 3]
    const float* __restrict__ EtaR,      // [1]
    const float* __restrict__ ShfR,      // [NR]
    const float* __restrict__ EtaA,      // [1]
    const float* __restrict__ Zeta,      // [1]
    const float* __restrict__ ShfA,      // [NAA]
    const float* __restrict__ ShfZ,      // [NZ]
    float*       __restrict__ out)       // [B, A, OUTD]
{
    // unified compacted neighbor lists
    __shared__ float4 avec[AA];         // angular: unit dx,dy,dz, d
    __shared__ float  afcs[AA];         // angular: fc
    __shared__ int    aspc[AA];         // angular: species
    __shared__ float2 rlst[AA];         // radial:  d, fc
    __shared__ int    rspc[AA];         // radial:  species
    __shared__ int    cntR, cntA;

    const int tid  = threadIdx.x;
    const int wid  = tid >> 5;
    const int lane = tid & 31;
    const int aidx = blockIdx.x;
    const int i    = aidx % AA;
    const int b    = aidx / AA;

    float* o = out + (size_t)aidx * OUTD;
    // zero this CTA's private output slice (OUTD == blockDim == 384);
    // visible to all block threads after barrier #1/#2 (sync orders gmem too)
    o[tid] = 0.0f;

    // ---- params -> registers ----
    const float etaR = EtaR[0];
    const float etaA = EtaA[0];
    const float zeta = Zeta[0];
    const float shfr = ShfR[tid & 15];          // constant per thread (384 % 16 == 0)
    const float shfa = ShfA[lane >> 3];         // angular feature (a,z)
    const float shz  = ShfZ[lane & 7];
    const float cz   = __cosf(shz);
    const float sz   = __sinf(shz);

    if (tid == 383) { cntR = 0; cntA = 0; }

    // ---- distances in registers (threads 0..47) ----
    float uxr=0, uyr=0, uzr=0, drr=0, fcrv=0, fcav=0;
    bool  pvR=false, pvA=false;
    int   spj=0;
    if (tid < AA) {
        int j = tid;
        const float* cb = coords + (size_t)b*AA*3;
        float xi = cb[3*i], yi = cb[3*i+1], zi = cb[3*i+2];
        float dx = xi - cb[3*j], dy = yi - cb[3*j+1], dz = zi - cb[3*j+2];
        float d2 = dx*dx + dy*dy + dz*dz;
        float d  = sqrtf(d2);
        spj = species[b*AA + j];
        int spi = species[b*AA + i];
        bool pv = (spi >= 0) && (spj >= 0) && (j != i);
        drr = d;
        pvR = pv && (d <= RCR);
        pvA = pv && (d <= RCA);
        fcrv = 0.5f*__cosf(PI_F * d * (1.0f/RCR)) + 0.5f;
        fcav = 0.5f*__cosf(PI_F * d * (1.0f/RCA)) + 0.5f;
        float invd = __frsqrt_rn(fmaxf(d2, 1e-12f));
        uxr = dx*invd; uyr = dy*invd; uzr = dz*invd;
    }
    __syncthreads();   // #1: counters + zeroed slice visible

    // ---- compaction (unified lists) ----
    if (tid < AA) {
        if (pvR) {
            int s = atomicAdd(&cntR, 1);
            rlst[s] = make_float2(drr, fcrv);
            rspc[s] = spj;
        }
        if (pvA) {
            int s = atomicAdd(&cntA, 1);
            avec[s] = make_float4(uxr, uyr, uzr, drr);
            afcs[s] = fcav;
            aspc[s] = spj;
        }
    }
    __syncthreads();   // #2: lists ready

    const int M      = cntA;
    const int Mr     = cntR;
    const int npair2 = M*(M-1)/2;
    const float twoM1 = (float)(2*M - 1);

    // ---- radial: thread-item pool, RED accumulate (r = tid&15 fixed) ----
    for (int w = tid; w < Mr*NR; w += 384) {
        int k = w >> 4;
        float2 v  = rlst[k];
        float  dd = v.x - shfr;
        atomicAdd(&o[rspc[k]*NR + (tid & 15)],
                  0.25f * __expf(-etaR * dd * dd) * v.y);
    }

    // ---- angular: all 12 warps draw from the unified pair pool ----
    for (int u = wid; u < npair2; u += 12) {
        // closed-form decode of (p,q), warp-uniform
        float disc = fmaxf(twoM1*twoM1 - 8.0f*(float)u, 0.0f);
        int p = (int)floorf((twoM1 - __fsqrt_rn(disc)) * 0.5f);
        if (p > M-2) p = M-2;
        if ((p+1)*(2*M - p - 2) / 2 <= u) p++;
        if (p*(2*M - p - 1) / 2 > u) p--;
        int q = u - p*(2*M - p - 1)/2 + p + 1;

        float4 P = avec[p];
        float4 Q = avec[q];
        float fcp = afcs[p], fcq = afcs[q];
        float cosA = 0.95f * (P.x*Q.x + P.y*Q.y + P.z*Q.z);
        float sinA = sqrtf(fmaxf(1.0f - cosA*cosA, 0.0f));
        float t    = 0.5f*(P.w + Q.w) - shfa;
        float f2   = 2.0f * fcp * fcq * __expf(-etaA * t * t);
        float x    = 0.5f + 0.5f*(cosA*cz + sinA*sz);
        float f1;
        if (zeta == 32.0f) {
            float x2 = x*x, x4 = x2*x2, x8 = x4*x4, x16 = x8*x8;
            f1 = x16*x16;
        } else {
            f1 = __powf(x, zeta);
        }

        int s1 = aspc[p], s2 = aspc[q];
        int lo = min(s1, s2), hi = max(s1, s2);
        int pidx = lo*SS - (lo*(lo-1))/2 + (hi - lo);

        atomicAdd(&o[RADD + pidx*32 + lane], f1 * f2);
    }
    // no final barrier, no store phase — warps retire independently
}

extern "C" void kernel_launch(void* const* d_in, const int* in_sizes, int n_in,
                              void* d_out, int out_size)
{
    const int*   species = (const int*)  d_in[0];
    const float* coords  = (const float*)d_in[1];
    const float* EtaR    = (const float*)d_in[2];
    const float* ShfR    = (const float*)d_in[3];
    const float* EtaA    = (const float*)d_in[4];
    const float* Zeta    = (const float*)d_in[5];
    const float* ShfA    = (const float*)d_in[6];
    const float* ShfZ    = (const float*)d_in[7];
    float* out = (float*)d_out;

    int B = in_sizes[0] / AA;   // species is [B, A]
    aev_kernel<<<B * AA, 384>>>(species, coords, EtaR, ShfR, EtaA, Zeta,
                                ShfA, ShfZ, out);
}